// round 4
// baseline (speedup 1.0000x reference)
#include <cuda_runtime.h>
#include <math.h>

#define Bb 64
#define Ll 128
#define Hh 128
#define Dd 16
#define NTOT (Bb*Ll*Ll)        // 1048576

typedef unsigned long long u64;

// ---------------- scratch ----------------
__device__ float g_Wt[Hh*Dd*Hh];            // [k][d*128+n]   1 MB
__device__ float g_Wrt[Dd*Hh];              // [d*128+n]
__device__ float g_Q[(size_t)Bb*Ll*Dd*Hh];  // [b][j][d*128+n] 64 MB
__device__ float g_c[Bb*Ll*Dd];             // [b][j][d]
__device__ float g_LP[2u*NTOT];             // partial logits [dhalf][b][j][m] 8 MB

// ---------------- packed f32x2 helpers ----------------
__device__ __forceinline__ u64 ffma2(u64 a, u64 b, u64 c) {
    u64 d; asm("fma.rn.f32x2 %0, %1, %2, %3;" : "=l"(d) : "l"(a), "l"(b), "l"(c));
    return d;
}
__device__ __forceinline__ u64 fadd2(u64 a, u64 b) {
    u64 d; asm("add.rn.f32x2 %0, %1, %2;" : "=l"(d) : "l"(a), "l"(b));
    return d;
}
__device__ __forceinline__ u64 dup2(float v) {
    u64 d; asm("mov.b64 %0, {%1, %2};" : "=l"(d) : "f"(v), "f"(v));
    return d;
}
__device__ __forceinline__ float2 unpack2(u64 v) {
    float2 r; asm("mov.b64 {%0, %1}, %2;" : "=f"(r.x), "=f"(r.y) : "l"(v));
    return r;
}

// ---------------- JAX threefry2x32, partitionable, key=(0,1) ----------------
__device__ __forceinline__ unsigned int rotl32(unsigned int v, int s) {
    return (v << s) | (v >> (32 - s));
}
__device__ __forceinline__ unsigned int threefry_bits(unsigned int i) {
    const unsigned int ks0 = 0u, ks1 = 1u, ks2 = 0x1BD11BDAu ^ 0u ^ 1u;
    unsigned int x0 = 0u + ks0;
    unsigned int x1 = i + ks1;
#define TFR(r) { x0 += x1; x1 = rotl32(x1, r) ^ x0; }
    TFR(13) TFR(15) TFR(26) TFR(6)   x0 += ks1; x1 += ks2 + 1u;
    TFR(17) TFR(29) TFR(16) TFR(24)  x0 += ks2; x1 += ks0 + 2u;
    TFR(13) TFR(15) TFR(26) TFR(6)   x0 += ks0; x1 += ks1 + 3u;
    TFR(17) TFR(29) TFR(16) TFR(24)  x0 += ks1; x1 += ks2 + 4u;
    TFR(13) TFR(15) TFR(26) TFR(6)   x0 += ks2; x1 += ks0 + 5u;
#undef TFR
    return x0 ^ x1;
}

__device__ __forceinline__ float tanh_fast(float x) {
    float e = __expf(2.0f * x);
    return 1.0f - __fdividef(2.0f, e + 1.0f);
}

// ---------------- kernel T: W[k,n,d] -> Wt[k, d*128+n]; Wr[n,d] -> Wrt ----
__global__ void k_transpose(const float* __restrict__ W, const float* __restrict__ Wr) {
    int idx = blockIdx.x * blockDim.x + threadIdx.x;
    if (idx < Hh * Hh * Dd) {
        int k = idx >> 11;
        int rem = idx & 2047;
        int d = rem >> 7;
        int n = rem & 127;
        g_Wt[idx] = W[(k * Hh + n) * Dd + d];
    }
    if (idx < Dd * Hh) {
        int d = idx >> 7, n = idx & 127;
        g_Wrt[idx] = Wr[n * Dd + d];
    }
}

// ---------------- kernel C: c[b,j,d] = enc[b,j,:].Wl[:,d] + Bvec[d] ----
__global__ void k_linear(const float* __restrict__ enc, const float* __restrict__ Wl,
                         const float* __restrict__ Bvec) {
    int idx = blockIdx.x * blockDim.x + threadIdx.x;
    if (idx >= Bb * Ll * Dd) return;
    int d = idx & 15;
    int bj = idx >> 4;
    const float* e = enc + (size_t)bj * Hh;
    float acc = Bvec[d];
#pragma unroll 8
    for (int k = 0; k < Hh; k++) acc = fmaf(e[k], Wl[k * Dd + d], acc);
    g_c[idx] = acc;
}

// swizzled float4 slot: row r (0..127), slot s (0..31)
#define SWZ(r, s) ((r) * 32 + ((s) ^ ((r) & 31)))

#define ROWOP(r, aval) { u64 a_ = dup2(aval); \
    acc[r][0] = ffma2(a_, b01.x, acc[r][0]); \
    acc[r][1] = ffma2(a_, b01.y, acc[r][1]); \
    acc[r][2] = ffma2(a_, b23.x, acc[r][2]); \
    acc[r][3] = ffma2(a_, b23.y, acc[r][3]); }

// ---------------- kernel 1: Q[b,j,128*d + n] = enc_b @ Wt + Wrt ----------
// grid (16 = d, 64 = b), block 256, 8x8 per thread, FFMA2
extern __shared__ char smemG[];
__global__ __launch_bounds__(256) void k_gemm1(const float* __restrict__ enc) {
    float4* sA  = (float4*)smemG;            // swizzled enc^T [k][j-slot] 64KB
    float4* sB4 = (float4*)(smemG + 65536);  // [k][c] plain 64KB
    int b = blockIdx.y;
    int col0 = blockIdx.x * 128;             // = d*128
    int tid = threadIdx.x;
    int tx = tid & 15, ty = tid >> 4;        // cblk = tx*8, jblk = ty*8

    // load + transpose-swizzle A (enc_b): src rows j, cols k -> sA[k][j]
    {
        const float4* e4 = (const float4*)(enc + (size_t)b * Ll * Hh);
        float* base = (float*)sA;
        for (int idx = tid; idx < 4096; idx += 256) {
            int j = idx >> 5, ng = idx & 31;
            float4 v = e4[j * 32 + ng];
            int s = j >> 2, lo = j & 3;
            int k0 = ng * 4;
            base[SWZ(k0 + 0, s) * 4 + lo] = v.x;
            base[SWZ(k0 + 1, s) * 4 + lo] = v.y;
            base[SWZ(k0 + 2, s) * 4 + lo] = v.z;
            base[SWZ(k0 + 3, s) * 4 + lo] = v.w;
        }
    }
    // load B tile: Wt[k][col0 + c], plain row-major
    {
        const float4* w4 = (const float4*)g_Wt;
        for (int idx = tid; idx < 4096; idx += 256) {
            int k = idx >> 5, cg = idx & 31;
            sB4[k * 32 + cg] = w4[k * 512 + (col0 >> 2) + cg];
        }
    }
    __syncthreads();

    u64 acc[8][4];
#pragma unroll
    for (int r = 0; r < 8; r++)
#pragma unroll
        for (int q = 0; q < 4; q++) acc[r][q] = 0ull;

    const ulonglong2* sB2 = (const ulonglong2*)sB4;
#pragma unroll 4
    for (int k = 0; k < 128; k++) {
        int x = k & 31;
        float4 a01 = sA[k * 32 + ((2 * ty) ^ x)];
        float4 a23 = sA[k * 32 + ((2 * ty + 1) ^ x)];
        ulonglong2 b01 = sB2[k * 32 + 2 * tx];
        ulonglong2 b23 = sB2[k * 32 + 2 * tx + 1];
        ROWOP(0, a01.x) ROWOP(1, a01.y) ROWOP(2, a01.z) ROWOP(3, a01.w)
        ROWOP(4, a23.x) ROWOP(5, a23.y) ROWOP(6, a23.z) ROWOP(7, a23.w)
    }

    // epilogue: + Wrt, store Q
    ulonglong2 wr01 = *(const ulonglong2*)(g_Wrt + col0 + tx * 8);
#pragma unroll
    for (int r = 0; r < 8; r++) {
        int j = ty * 8 + r;
        ulonglong2 o0, o1;
        o0.x = fadd2(acc[r][0], wr01.x);
        o0.y = fadd2(acc[r][1], wr01.y);
        float* dst = g_Q + (size_t)(b * Ll + j) * 2048 + col0 + tx * 8;
        *(ulonglong2*)dst = o0;
        (void)o1;
    }
    // second half of each row's 8 cols is in acc[r][2..3] minus wr upper pair:
    // (handled above only for cols 0..3; do cols 4..7 now)
    ulonglong2 wr23 = *(const ulonglong2*)(g_Wrt + col0 + tx * 8 + 4);
#pragma unroll
    for (int r = 0; r < 8; r++) {
        int j = ty * 8 + r;
        ulonglong2 o;
        o.x = fadd2(acc[r][2], wr23.x);
        o.y = fadd2(acc[r][3], wr23.y);
        float* dst = g_Q + (size_t)(b * Ll + j) * 2048 + col0 + tx * 8 + 4;
        *(ulonglong2*)dst = o;
    }
}

// ---------------- kernel 2: bilinear GEMM + tanh + partial logits --------
// grid (2 = d-half, 64 = b), block 256; j=128 x m=128 tile; FFMA2
extern __shared__ char smemF[];
__global__ __launch_bounds__(256) void k_final(const float* __restrict__ enc,
                                               const float* __restrict__ U) {
    float4* sE  = (float4*)smemF;              // swizzled enc^T [n][m-slot] 64KB
    float4* sQT = (float4*)(smemF + 65536);    // swizzled Q^T [n][j-slot] 64KB (per d)
    float*  sC  = (float*)(smemF + 131072);    // c[b] slice [j][d] 8KB
    float*  sU  = (float*)(smemF + 131072 + 8192);
    int dx = blockIdx.x;                       // d-half
    int b = blockIdx.y;
    int tid = threadIdx.x;
    int tx = tid & 15, ty = tid >> 4;          // mblk = tx*8, jblk = ty*8

    // stage sE (enc_b transposed: rows n, cols m), sC, sU
    {
        const float4* e4 = (const float4*)(enc + (size_t)b * Ll * Hh);
        float* base = (float*)sE;
        for (int idx = tid; idx < 4096; idx += 256) {
            int m = idx >> 5, ng = idx & 31;
            float4 v = e4[m * 32 + ng];
            int s = m >> 2, lo = m & 3;
            int n0 = ng * 4;
            base[SWZ(n0 + 0, s) * 4 + lo] = v.x;
            base[SWZ(n0 + 1, s) * 4 + lo] = v.y;
            base[SWZ(n0 + 2, s) * 4 + lo] = v.z;
            base[SWZ(n0 + 3, s) * 4 + lo] = v.w;
        }
        for (int idx = tid; idx < 2048; idx += 256) sC[idx] = g_c[b * 2048 + idx];
        if (tid < 16) sU[tid] = U[tid];
    }

    float logit[8][8];
#pragma unroll
    for (int r = 0; r < 8; r++)
#pragma unroll
        for (int q = 0; q < 8; q++) logit[r][q] = 0.0f;

    for (int dd = 0; dd < 8; dd++) {
        int d = dx * 8 + dd;
        __syncthreads();   // sE/sC ready (first iter); prev compute done before overwrite
        // stage sQT: Q slice [j][n] -> [n][j] swizzled
        {
            const float4* q4 = (const float4*)(g_Q + (size_t)b * Ll * 2048 + d * 128);
            float* base = (float*)sQT;
            for (int idx = tid; idx < 4096; idx += 256) {
                int j = idx >> 5, ng = idx & 31;
                float4 v = q4[j * 512 + ng];
                int s = j >> 2, lo = j & 3;
                int n0 = ng * 4;
                base[SWZ(n0 + 0, s) * 4 + lo] = v.x;
                base[SWZ(n0 + 1, s) * 4 + lo] = v.y;
                base[SWZ(n0 + 2, s) * 4 + lo] = v.z;
                base[SWZ(n0 + 3, s) * 4 + lo] = v.w;
            }
        }
        __syncthreads();

        u64 acc[8][4];
#pragma unroll
        for (int r = 0; r < 8; r++)
#pragma unroll
            for (int q = 0; q < 4; q++) acc[r][q] = 0ull;

        const ulonglong2* sE2 = (const ulonglong2*)sE;
#pragma unroll 4
        for (int n = 0; n < 128; n++) {
            int x = n & 31;
            float4 a01 = sQT[n * 32 + ((2 * ty) ^ x)];
            float4 a23 = sQT[n * 32 + ((2 * ty + 1) ^ x)];
            ulonglong2 b01 = sE2[n * 32 + ((2 * tx) ^ x)];
            ulonglong2 b23 = sE2[n * 32 + ((2 * tx + 1) ^ x)];
            ROWOP(0, a01.x) ROWOP(1, a01.y) ROWOP(2, a01.z) ROWOP(3, a01.w)
            ROWOP(4, a23.x) ROWOP(5, a23.y) ROWOP(6, a23.z) ROWOP(7, a23.w)
        }

        float ud = sU[d];
#pragma unroll
        for (int r = 0; r < 8; r++) {
            float cr = sC[(ty * 8 + r) * 16 + d];
#pragma unroll
            for (int qp = 0; qp < 4; qp++) {
                float2 s = unpack2(acc[r][qp]);
                logit[r][2 * qp]     = fmaf(ud, tanh_fast(s.x + cr), logit[r][2 * qp]);
                logit[r][2 * qp + 1] = fmaf(ud, tanh_fast(s.y + cr), logit[r][2 * qp + 1]);
            }
        }
    }

    // write partial logits [dx][b][j][m]
#pragma unroll
    for (int r = 0; r < 8; r++) {
        int j = ty * 8 + r;
        size_t o = ((size_t)(dx * Bb + b) * Ll + j) * Ll + tx * 8;
        *(float4*)(g_LP + o)     = make_float4(logit[r][0], logit[r][1], logit[r][2], logit[r][3]);
        *(float4*)(g_LP + o + 4) = make_float4(logit[r][4], logit[r][5], logit[r][6], logit[r][7]);
    }
}

// ---------------- kernel E: combine partials + mask/sigmoid/RNG/entropy ---
__global__ __launch_bounds__(256) void k_epi(const float* __restrict__ lb,
                                             float* __restrict__ out) {
    int gid = blockIdx.x * blockDim.x + threadIdx.x;   // < NTOT/4
    const float4* P0 = (const float4*)g_LP;
    const float4* P1 = P0 + (NTOT / 4);
    float4 a = P0[gid], c = P1[gid];
    float lbias = lb[0];
    float s4[4] = { a.x + c.x + lbias, a.y + c.y + lbias,
                    a.z + c.z + lbias, a.w + c.w + lbias };
    int flat0 = gid * 4;
    int j = (flat0 >> 7) & 127;
    int m0 = flat0 & 127;
    float vs[4], ve[4];
#pragma unroll
    for (int e = 0; e < 4; e++) {
        float s = s4[e];
        if (j == m0 + e) s -= 1e8f;
        s4[e] = s;
        float p = 1.0f / (1.0f + expf(-s));
        unsigned int bits = threefry_bits((unsigned int)(flat0 + e));
        float u = __uint_as_float((bits >> 9) | 0x3f800000u) - 1.0f;
        vs[e] = (u < p) ? 1.0f : 0.0f;
        float ax = fabsf(s);
        float lse = log1pf(expf(-ax));
        float spp = fmaxf(s, 0.0f) + lse;
        float spn = fmaxf(-s, 0.0f) + lse;
        ve[e] = p * spn + (1.0f - p) * spp;
    }
    ((float4*)out)[gid]                = make_float4(vs[0], vs[1], vs[2], vs[3]);
    ((float4*)(out + NTOT))[gid]       = make_float4(s4[0], s4[1], s4[2], s4[3]);
    ((float4*)(out + 2u * NTOT))[gid]  = make_float4(ve[0], ve[1], ve[2], ve[3]);
}

// ---------------- launch ----------------
extern "C" void kernel_launch(void* const* d_in, const int* in_sizes, int n_in,
                              void* d_out, int out_size) {
    const float* enc  = (const float*)d_in[0];
    const float* W    = (const float*)d_in[1];
    const float* Wl   = (const float*)d_in[2];
    const float* Wr   = (const float*)d_in[3];
    const float* U    = (const float*)d_in[4];
    const float* Bv   = (const float*)d_in[5];
    const float* lbias= (const float*)d_in[6];
    float* out = (float*)d_out;

    k_transpose<<<(Hh * Hh * Dd + 255) / 256, 256>>>(W, Wr);
    k_linear<<<(Bb * Ll * Dd + 255) / 256, 256>>>(enc, Wl, Bv);

    int smemG_bytes = 131072;
    cudaFuncSetAttribute(k_gemm1, cudaFuncAttributeMaxDynamicSharedMemorySize, smemG_bytes);
    k_gemm1<<<dim3(16, Bb), 256, smemG_bytes>>>(enc);

    int smemF_bytes = 131072 + 8192 + 64;
    cudaFuncSetAttribute(k_final, cudaFuncAttributeMaxDynamicSharedMemorySize, smemF_bytes);
    k_final<<<dim3(2, Bb), 256, smemF_bytes>>>(enc, U);

    k_epi<<<NTOT / 4 / 256, 256>>>(lbias, out);
}